// round 2
// baseline (speedup 1.0000x reference)
#include <cuda_runtime.h>

// Problem constants (fixed by the dataset shapes)
#define HWC   65536      // 256*256
#define BATCH 64
#define NATT  4096
#define MREP  2048

#define ATT_BLOCKS ((BATCH * NATT) / 256)   // 1024
#define REP_BLOCKS ((BATCH * MREP) / 256)   // 512
#define TOT_BLOCKS (ATT_BLOCKS + REP_BLOCKS)

// Global accumulators: [0]=S_attract, [1]=N_attract, [2]=S_repel, [3]=N_repel
// Zero-initialized at module load; the finalizing block re-zeros them each call
// so graph replays are deterministic.
__device__ double g_acc[4];
__device__ unsigned int g_done;

__device__ __forceinline__ float iou_f(float hA, float yA, float xA,
                                       float hB, float yB, float xB) {
    float areaA = hA * hA * 0.41f;
    float areaB = hB * hB * 0.41f;
    float y_min_max = fmaxf(yA - hA * 0.5f,         yB - hB * 0.5f);
    float x_min_max = fmaxf(xA - 0.41f * hA * 0.5f, xB - 0.41f * hB * 0.5f);
    float y_max_min = fminf(yA + hA * 0.5f,         yB + hB * 0.5f);
    float x_max_min = fminf(xA + 0.41f * hA * 0.5f, xB + 0.41f * hB * 0.5f);
    float I = fmaxf(y_max_min - y_min_max, 0.0f) * fmaxf(x_max_min - x_min_max, 0.0f);
    float U = areaA + areaB - I;
    return I / (U + 1e-6f);
}

// Block-wide reduction of (v0, v1); returns true partials in lane0/warp0.
__device__ __forceinline__ void block_reduce2(float v0, float v1,
                                              double* acc0, double* acc1) {
    #pragma unroll
    for (int o = 16; o > 0; o >>= 1) {
        v0 += __shfl_down_sync(0xFFFFFFFFu, v0, o);
        v1 += __shfl_down_sync(0xFFFFFFFFu, v1, o);
    }
    __shared__ float s0[8], s1[8];
    int lane = threadIdx.x & 31;
    int warp = threadIdx.x >> 5;
    if (lane == 0) { s0[warp] = v0; s1[warp] = v1; }
    __syncthreads();
    if (warp == 0) {
        v0 = (lane < 8) ? s0[lane] : 0.0f;
        v1 = (lane < 8) ? s1[lane] : 0.0f;
        #pragma unroll
        for (int o = 4; o > 0; o >>= 1) {
            v0 += __shfl_down_sync(0x000000FFu, v0, o);
            v1 += __shfl_down_sync(0x000000FFu, v1, o);
        }
        if (lane == 0) {
            atomicAdd(acc0, (double)v0);
            atomicAdd(acc1, (double)v1);
        }
    }
}

__global__ __launch_bounds__(256)
void fused_iou_loss_kernel(const float* __restrict__ oh,
                           const float* __restrict__ ooff,
                           const float* __restrict__ pre_off,
                           const int*   __restrict__ attract,
                           const int*   __restrict__ repel,
                           const unsigned char* __restrict__ mask_att,
                           const unsigned char* __restrict__ mask_rep,
                           float* __restrict__ out) {
    if (blockIdx.x < ATT_BLOCKS) {
        // ---------------- attract branch: one thread per (b, n) ----------------
        int gid = blockIdx.x * 256 + threadIdx.x;   // b*NATT + n
        int b   = gid >> 12;                        // / 4096

        int4 idx4 = reinterpret_cast<const int4*>(attract)[gid];
        unsigned int m4 = reinterpret_cast<const unsigned int*>(mask_att)[gid];

        const float* ohb = oh   + (size_t)b * HWC;
        const float* o0b = ooff + (size_t)b * 2 * HWC;
        const float* o1b = o0b + HWC;

        int ind[4] = {idx4.x, idx4.y, idx4.z, idx4.w};
        float h[4], o0[4], o1[4];
        #pragma unroll
        for (int k = 0; k < 4; k++) {
            h[k]  = __ldg(ohb + ind[k]);
            o0[k] = __ldg(o0b + ind[k]);
            o1[k] = __ldg(o1b + ind[k]);
        }

        // OFFSETS = [[0,0],[1,0],[0,1],[1,1]] added to (o0, o1)
        const float kx[4] = {0.f, 1.f, 0.f, 1.f};
        const float ky[4] = {0.f, 0.f, 1.f, 1.f};

        float hm = 0.f, o0m = 0.f, o1m = 0.f;
        #pragma unroll
        for (int k = 0; k < 4; k++) {
            o0[k] += kx[k];
            o1[k] += ky[k];
            hm  += h[k];
            o0m += o0[k];
            o1m += o1[k];
        }
        hm *= 0.25f; o0m *= 0.25f; o1m *= 0.25f;
        float hB = expf(hm);

        float lsum = 0.f, cnt = 0.f;
        #pragma unroll
        for (int k = 0; k < 4; k++) {
            if ((m4 >> (8 * k)) & 0xFFu) {
                lsum += 1.0f - iou_f(expf(h[k]), o0[k], o1[k], hB, o0m, o1m);
                cnt  += 1.0f;
            }
        }
        block_reduce2(lsum, cnt, &g_acc[0], &g_acc[1]);
    } else {
        // ---------------- repel branch: one thread per (b, m) ----------------
        int gid = (blockIdx.x - ATT_BLOCKS) * 256 + threadIdx.x;  // b*MREP + m
        int b   = gid >> 11;                                      // / 2048

        const int4* rp = reinterpret_cast<const int4*>(repel) + (size_t)gid * 2;
        int4 i0 = rp[0];
        int4 i1 = rp[1];

        const float* ohb = oh   + (size_t)b * HWC;
        const float* o0b = ooff + (size_t)b * 2 * HWC;
        const float* o1b = o0b + HWC;

        int ind[8] = {i0.x, i0.y, i0.z, i0.w, i1.x, i1.y, i1.z, i1.w};
        float hs[8], a0[8], a1[8];
        #pragma unroll
        for (int k = 0; k < 8; k++) {
            hs[k] = __ldg(ohb + ind[k]);
            a0[k] = __ldg(o0b + ind[k]);
            a1[k] = __ldg(o1b + ind[k]);
        }

        float hmean[2], y[2], x[2];
        #pragma unroll
        for (int j = 0; j < 2; j++) {
            float hsum = 0.f, s0 = 0.f, s1 = 0.f;
            #pragma unroll
            for (int k = 0; k < 4; k++) {
                hsum += hs[j * 4 + k];
                s0   += a0[j * 4 + k];
                s1   += a1[j * 4 + k];
            }
            hmean[j] = hsum * 0.25f;
            // mean of (off + OFFSETS): OFFSETS contributes +0.5 per channel
            y[j] = s0 * 0.25f + 0.5f;
            x[j] = s1 * 0.25f + 0.5f;
        }
        float2 po = reinterpret_cast<const float2*>(pre_off)[gid];
        y[1] += po.x;
        x[1] += po.y;

        float v = iou_f(expf(hmean[0]), y[0], x[0], expf(hmean[1]), y[1], x[1]);

        float lsum = 0.f, cnt = 0.f;
        if (mask_rep[gid]) { lsum = v; cnt = 1.0f; }
        block_reduce2(lsum, cnt, &g_acc[2], &g_acc[3]);
    }

    // ---------------- last-block finalize + reset ----------------
    __threadfence();
    __shared__ bool s_last;
    if (threadIdx.x == 0) {
        unsigned int ticket = atomicAdd(&g_done, 1u);
        s_last = (ticket == (unsigned int)(TOT_BLOCKS - 1));
    }
    __syncthreads();
    if (s_last && threadIdx.x == 0) {
        // All other blocks' atomics are visible (they fenced before ticketing).
        double sa = g_acc[0], na = g_acc[1];
        double sr = g_acc[2], nr = g_acc[3];
        out[0] = (float)(sa / (na + 1e-4) + sr / (nr + 1e-4));
        // Reset for the next (graph-replayed) call — deterministic state.
        g_acc[0] = 0.0; g_acc[1] = 0.0; g_acc[2] = 0.0; g_acc[3] = 0.0;
        __threadfence();
        g_done = 0u;
    }
}

extern "C" void kernel_launch(void* const* d_in, const int* in_sizes, int n_in,
                              void* d_out, int out_size) {
    const float* output_h    = (const float*)d_in[0];  // [64,1,256,256]
    const float* output_off  = (const float*)d_in[1];  // [64,2,256,256]
    // d_in[2], d_in[3]: target_h / target_off — unused by the reference
    const float* pre_off     = (const float*)d_in[4];  // [64,2048,2]
    const int*   attract     = (const int*)  d_in[5];  // [64,4096,4]
    const int*   repel       = (const int*)  d_in[6];  // [64,2048,2,4]
    const unsigned char* mask_attract = (const unsigned char*)d_in[7];  // [64,4096,4] bool
    const unsigned char* mask_repel   = (const unsigned char*)d_in[8];  // [64,2048,1] bool
    float* out = (float*)d_out;

    fused_iou_loss_kernel<<<TOT_BLOCKS, 256>>>(
        output_h, output_off, pre_off, attract, repel,
        mask_attract, mask_repel, out);
}

// round 3
// speedup vs baseline: 1.0838x; 1.0838x over previous
#include <cuda_runtime.h>

// Problem constants (fixed by the dataset shapes)
#define HWC   65536      // 256*256
#define BATCH 64
#define NATT  4096
#define MREP  2048

// Balanced single-wave grid: every thread does exactly 24 gathers.
// blocks [0, REP_BLOCKS): 1 repel item/thread (24 loads)
// blocks [REP_BLOCKS, TOT_BLOCKS): 2 attract items/thread (2x12 loads)
#define REP_BLOCKS ((BATCH * MREP) / 256)        // 512
#define ATT_BLOCKS ((BATCH * NATT) / (2 * 256))  // 512
#define TOT_BLOCKS (REP_BLOCKS + ATT_BLOCKS)     // 1024

// Global accumulators: [0]=S_attract, [1]=N_attract, [2]=S_repel, [3]=N_repel
// Zero-initialized at module load; the finalizing block re-zeros them each call
// so graph replays are deterministic.
__device__ double g_acc[4];
__device__ unsigned int g_done;

__device__ __forceinline__ float iou_f(float hA, float yA, float xA,
                                       float hB, float yB, float xB) {
    float areaA = hA * hA * 0.41f;
    float areaB = hB * hB * 0.41f;
    float y_min_max = fmaxf(yA - hA * 0.5f,         yB - hB * 0.5f);
    float x_min_max = fmaxf(xA - 0.41f * hA * 0.5f, xB - 0.41f * hB * 0.5f);
    float y_max_min = fminf(yA + hA * 0.5f,         yB + hB * 0.5f);
    float x_max_min = fminf(xA + 0.41f * hA * 0.5f, xB + 0.41f * hB * 0.5f);
    float I = fmaxf(y_max_min - y_min_max, 0.0f) * fmaxf(x_max_min - x_min_max, 0.0f);
    float U = areaA + areaB - I;
    return I / (U + 1e-6f);
}

// Block-wide reduction of (v0, v1) -> double atomics. blockDim.x == 256.
__device__ __forceinline__ void block_reduce2(float v0, float v1,
                                              double* acc0, double* acc1) {
    #pragma unroll
    for (int o = 16; o > 0; o >>= 1) {
        v0 += __shfl_down_sync(0xFFFFFFFFu, v0, o);
        v1 += __shfl_down_sync(0xFFFFFFFFu, v1, o);
    }
    __shared__ float s0[8], s1[8];
    int lane = threadIdx.x & 31;
    int warp = threadIdx.x >> 5;
    if (lane == 0) { s0[warp] = v0; s1[warp] = v1; }
    __syncthreads();
    if (warp == 0) {
        v0 = (lane < 8) ? s0[lane] : 0.0f;
        v1 = (lane < 8) ? s1[lane] : 0.0f;
        #pragma unroll
        for (int o = 4; o > 0; o >>= 1) {
            v0 += __shfl_down_sync(0x000000FFu, v0, o);
            v1 += __shfl_down_sync(0x000000FFu, v1, o);
        }
        if (lane == 0) {
            atomicAdd(acc0, (double)v0);
            atomicAdd(acc1, (double)v1);
        }
    }
}

// One attract item: 12 gathers + per-corner IoU against the mean box.
__device__ __forceinline__ void attract_item(int gid,
                                             const float* __restrict__ oh,
                                             const float* __restrict__ ooff,
                                             const int4 idx4, unsigned int m4,
                                             float& lsum, float& cnt) {
    int b = gid >> 12;  // / 4096
    const float* ohb = oh   + (size_t)b * HWC;
    const float* o0b = ooff + (size_t)b * 2 * HWC;
    const float* o1b = o0b + HWC;

    int ind[4] = {idx4.x, idx4.y, idx4.z, idx4.w};
    float h[4], o0[4], o1[4];
    #pragma unroll
    for (int k = 0; k < 4; k++) {
        h[k]  = __ldg(ohb + ind[k]);
        o0[k] = __ldg(o0b + ind[k]);
        o1[k] = __ldg(o1b + ind[k]);
    }

    // OFFSETS = [[0,0],[1,0],[0,1],[1,1]] added to (o0, o1)
    const float kx[4] = {0.f, 1.f, 0.f, 1.f};
    const float ky[4] = {0.f, 0.f, 1.f, 1.f};

    float hm = 0.f, o0m = 0.f, o1m = 0.f;
    #pragma unroll
    for (int k = 0; k < 4; k++) {
        o0[k] += kx[k];
        o1[k] += ky[k];
        hm  += h[k];
        o0m += o0[k];
        o1m += o1[k];
    }
    hm *= 0.25f; o0m *= 0.25f; o1m *= 0.25f;
    float hB = expf(hm);

    #pragma unroll
    for (int k = 0; k < 4; k++) {
        if ((m4 >> (8 * k)) & 0xFFu) {
            lsum += 1.0f - iou_f(expf(h[k]), o0[k], o1[k], hB, o0m, o1m);
            cnt  += 1.0f;
        }
    }
}

__global__ __launch_bounds__(256, 8)
void fused_iou_loss_kernel(const float* __restrict__ oh,
                           const float* __restrict__ ooff,
                           const float* __restrict__ pre_off,
                           const int*   __restrict__ attract,
                           const int*   __restrict__ repel,
                           const unsigned char* __restrict__ mask_att,
                           const unsigned char* __restrict__ mask_rep,
                           float* __restrict__ out) {
    if (blockIdx.x < REP_BLOCKS) {
        // ------------- repel branch: one thread per (b, m), 24 gathers -------------
        int gid = blockIdx.x * 256 + threadIdx.x;   // b*MREP + m
        int b   = gid >> 11;                        // / 2048

        const int4* rp = reinterpret_cast<const int4*>(repel) + (size_t)gid * 2;
        int4 i0 = rp[0];
        int4 i1 = rp[1];

        const float* ohb = oh   + (size_t)b * HWC;
        const float* o0b = ooff + (size_t)b * 2 * HWC;
        const float* o1b = o0b + HWC;

        int ind[8] = {i0.x, i0.y, i0.z, i0.w, i1.x, i1.y, i1.z, i1.w};
        float hs[8], a0[8], a1[8];
        #pragma unroll
        for (int k = 0; k < 8; k++) {
            hs[k] = __ldg(ohb + ind[k]);
            a0[k] = __ldg(o0b + ind[k]);
            a1[k] = __ldg(o1b + ind[k]);
        }

        float hmean[2], y[2], x[2];
        #pragma unroll
        for (int j = 0; j < 2; j++) {
            float hsum = 0.f, s0 = 0.f, s1 = 0.f;
            #pragma unroll
            for (int k = 0; k < 4; k++) {
                hsum += hs[j * 4 + k];
                s0   += a0[j * 4 + k];
                s1   += a1[j * 4 + k];
            }
            hmean[j] = hsum * 0.25f;
            // mean of (off + OFFSETS): OFFSETS contributes +0.5 per channel
            y[j] = s0 * 0.25f + 0.5f;
            x[j] = s1 * 0.25f + 0.5f;
        }
        float2 po = reinterpret_cast<const float2*>(pre_off)[gid];
        y[1] += po.x;
        x[1] += po.y;

        float v = iou_f(expf(hmean[0]), y[0], x[0], expf(hmean[1]), y[1], x[1]);

        float lsum = 0.f, cnt = 0.f;
        if (mask_rep[gid]) { lsum = v; cnt = 1.0f; }
        block_reduce2(lsum, cnt, &g_acc[2], &g_acc[3]);
    } else {
        // ----------- attract branch: two items per thread, 2x12 gathers -----------
        int w = (blockIdx.x - REP_BLOCKS) * 256 + threadIdx.x;  // [0, B*NATT/2)
        int gid0 = 2 * w;                                        // even item
        // Vector loads: two int4 indices (32B) and two 4-byte masks (8B).
        const int4* ap = reinterpret_cast<const int4*>(attract) + gid0;
        int4 idxA = ap[0];
        int4 idxB = ap[1];
        uint2 m2 = reinterpret_cast<const uint2*>(mask_att)[w];

        float lsum = 0.f, cnt = 0.f;
        attract_item(gid0,     oh, ooff, idxA, m2.x, lsum, cnt);
        attract_item(gid0 + 1, oh, ooff, idxB, m2.y, lsum, cnt);
        block_reduce2(lsum, cnt, &g_acc[0], &g_acc[1]);
    }

    // ---------------- last-block finalize + reset ----------------
    __threadfence();
    __shared__ bool s_last;
    if (threadIdx.x == 0) {
        unsigned int ticket = atomicAdd(&g_done, 1u);
        s_last = (ticket == (unsigned int)(TOT_BLOCKS - 1));
    }
    __syncthreads();
    if (s_last && threadIdx.x == 0) {
        double sa = g_acc[0], na = g_acc[1];
        double sr = g_acc[2], nr = g_acc[3];
        out[0] = (float)(sa / (na + 1e-4) + sr / (nr + 1e-4));
        g_acc[0] = 0.0; g_acc[1] = 0.0; g_acc[2] = 0.0; g_acc[3] = 0.0;
        __threadfence();
        g_done = 0u;
    }
}

extern "C" void kernel_launch(void* const* d_in, const int* in_sizes, int n_in,
                              void* d_out, int out_size) {
    const float* output_h    = (const float*)d_in[0];  // [64,1,256,256]
    const float* output_off  = (const float*)d_in[1];  // [64,2,256,256]
    // d_in[2], d_in[3]: target_h / target_off — unused by the reference
    const float* pre_off     = (const float*)d_in[4];  // [64,2048,2]
    const int*   attract     = (const int*)  d_in[5];  // [64,4096,4]
    const int*   repel       = (const int*)  d_in[6];  // [64,2048,2,4]
    const unsigned char* mask_attract = (const unsigned char*)d_in[7];  // [64,4096,4] bool
    const unsigned char* mask_repel   = (const unsigned char*)d_in[8];  // [64,2048,1] bool
    float* out = (float*)d_out;

    fused_iou_loss_kernel<<<TOT_BLOCKS, 256>>>(
        output_h, output_off, pre_off, attract, repel,
        mask_attract, mask_repel, out);
}